// round 11
// baseline (speedup 1.0000x reference)
#include <cuda_runtime.h>
#include <cuda_bf16.h>
#include <cstdint>

#define BB 2
#define HH 16
#define SS 2048
#define DD 64
#define SCL2E 0.1803368801111243f   /* (1/8) * log2(e) */
#define PADA 72
#define NQT 16
#define PLNB (64 * PADA * 2)
#define NQK ((size_t)BB * HH * SS * DD)
#define MROWB (SS / 8)              /* mask bits row stride: 256 bytes */

__device__ float g_st[BB * HH][SS][NQT];
__device__ int   g_mask_flag;
__device__ __nv_bfloat16 g_qh[NQK], g_ql[NQK], g_kh[NQK], g_kl[NQK];
__device__ unsigned long long g_maskbits[(size_t)BB * SS * SS / 64];   // 1 MB

// ---------------------------------------------------------------------------
__global__ void probe_mask_kernel(const void* m) {
    const unsigned int* w = (const unsigned int*)m;
    int lane = threadIdx.x;
    bool a01 = true, af = true;
    for (int i = lane * 32; i < lane * 32 + 32; i++) {
        unsigned int v = w[i];
        if (v != 0u && v != 1u) a01 = false;
        if (v != 0u && v != 0x3F800000u) af = false;
    }
    unsigned b1 = __ballot_sync(0xffffffffu, a01);
    unsigned b2 = __ballot_sync(0xffffffffu, af);
    if (lane == 0) g_mask_flag = (b1 == 0xffffffffu) ? 0 : ((b2 == 0xffffffffu) ? 1 : 2);
}

// ---------------------------------------------------------------------------
__device__ __forceinline__ uint32_t smem_u32(const void* p) {
    uint32_t a;
    asm("{ .reg .u64 t; cvta.to.shared.u64 t, %1; cvt.u32.u64 %0, t; }"
        : "=r"(a) : "l"(p));
    return a;
}

__device__ __forceinline__ void ldsm4(uint32_t* r, uint32_t addr) {
    asm volatile("ldmatrix.sync.aligned.m8n8.x4.shared.b16 {%0,%1,%2,%3}, [%4];"
                 : "=r"(r[0]), "=r"(r[1]), "=r"(r[2]), "=r"(r[3]) : "r"(addr));
}

__device__ __forceinline__ void ldsm4t(uint32_t* r, uint32_t addr) {
    asm volatile("ldmatrix.sync.aligned.m8n8.x4.trans.shared.b16 {%0,%1,%2,%3}, [%4];"
                 : "=r"(r[0]), "=r"(r[1]), "=r"(r[2]), "=r"(r[3]) : "r"(addr));
}

__device__ __forceinline__ void mma_bf16(float* c, const uint32_t* a,
                                         const uint32_t b0, const uint32_t b1) {
    asm volatile(
        "mma.sync.aligned.m16n8k16.row.col.f32.bf16.bf16.f32 "
        "{%0,%1,%2,%3}, {%4,%5,%6,%7}, {%8,%9}, {%0,%1,%2,%3};"
        : "+f"(c[0]), "+f"(c[1]), "+f"(c[2]), "+f"(c[3])
        : "r"(a[0]), "r"(a[1]), "r"(a[2]), "r"(a[3]), "r"(b0), "r"(b1));
}

__device__ __forceinline__ uint32_t pack2(__nv_bfloat16 a, __nv_bfloat16 b) {
    __nv_bfloat162 t(a, b);
    return *(uint32_t*)&t;
}

__device__ __forceinline__ void split4(float4 v, uint2& hi, uint2& lo) {
    __nv_bfloat16 hx = __float2bfloat16(v.x), hy = __float2bfloat16(v.y);
    __nv_bfloat16 hz = __float2bfloat16(v.z), hw = __float2bfloat16(v.w);
    hi.x = pack2(hx, hy);
    hi.y = pack2(hz, hw);
    lo.x = pack2(__float2bfloat16(v.x - __bfloat162float(hx)),
                 __float2bfloat16(v.y - __bfloat162float(hy)));
    lo.y = pack2(__float2bfloat16(v.z - __bfloat162float(hz)),
                 __float2bfloat16(v.w - __bfloat162float(hw)));
}

// ---------------------------------------------------------------------------
__global__ __launch_bounds__(256) void prep_qk_kernel(
    const float* __restrict__ Q, const float* __restrict__ K)
{
    size_t i4 = ((size_t)blockIdx.x * 256 + threadIdx.x) * 4;
    if (i4 >= NQK) return;
    uint2 hi, lo;
    split4(*(const float4*)&Q[i4], hi, lo);
    *(uint2*)&g_qh[i4] = hi;
    *(uint2*)&g_ql[i4] = lo;
    split4(*(const float4*)&K[i4], hi, lo);
    *(uint2*)&g_kh[i4] = hi;
    *(uint2*)&g_kl[i4] = lo;
}

// ---------------------------------------------------------------------------
// Prep: mask (any dtype) -> bit-packed (1 = masked). One uint32 per thread.
// ---------------------------------------------------------------------------
__global__ __launch_bounds__(256) void prep_mask_kernel(const void* __restrict__ m)
{
    const int flag = g_mask_flag;
    size_t w32 = (size_t)blockIdx.x * 256 + threadIdx.x;   // word index
    if (w32 >= (size_t)BB * SS * SS / 32) return;
    size_t e0 = w32 * 32;
    uint32_t bits = 0;
    if (flag == 2) {
        const unsigned char* mp = (const unsigned char*)m + e0;
#pragma unroll
        for (int q = 0; q < 2; q++) {
            uint4 w = *(const uint4*)&mp[q * 16];
            uint32_t ws[4] = {w.x, w.y, w.z, w.w};
#pragma unroll
            for (int k = 0; k < 4; k++)
#pragma unroll
                for (int bidx = 0; bidx < 4; bidx++)
                    if ((ws[k] >> (bidx * 8)) & 0xFF)
                        bits |= 1u << (q * 16 + k * 4 + bidx);
        }
    } else {
        const int* mp = (const int*)m + e0;
#pragma unroll
        for (int q = 0; q < 8; q++) {
            int4 w = *(const int4*)&mp[q * 4];
            if (w.x) bits |= 1u << (q * 4);
            if (w.y) bits |= 1u << (q * 4 + 1);
            if (w.z) bits |= 1u << (q * 4 + 2);
            if (w.w) bits |= 1u << (q * 4 + 3);
        }
    }
    ((uint32_t*)g_maskbits)[w32] = bits;
}

// ---------------------------------------------------------------------------
// QK: e = exp2(score*SCL2E) (0 where masked) -> attn; row sums -> g_st.
// CTA 128q x 128k; 8 warps 4(m) x 2(n). Mask read as 64-bit words from gmem.
// ---------------------------------------------------------------------------
__global__ __launch_bounds__(256, 2) void qk_mma_kernel(float* __restrict__ attn)
{
    extern __shared__ __align__(16) char smem[];
    __nv_bfloat16* Qh = (__nv_bfloat16*)smem;
    __nv_bfloat16* Ql = Qh + 128 * PADA;
    __nv_bfloat16* Kh = Ql + 128 * PADA;
    __nv_bfloat16* Kl = Kh + 128 * PADA;
    float* wreds = (float*)(Kl + 128 * PADA);   // [2][128]

    const int tid = threadIdx.x, lane = tid & 31, wid = tid >> 5;
    const int bh = blockIdx.z, b = bh >> 4;
    const int q0 = blockIdx.y * 128, k0 = blockIdx.x * 128;
    const int kt = blockIdx.x;

    const size_t qoff = ((size_t)bh * SS + q0) * DD;
    const size_t koff = ((size_t)bh * SS + k0) * DD;

    for (int i8 = tid; i8 < 128 * 8; i8 += 256) {
        int r = i8 >> 3, c8 = (i8 & 7) * 8;
        *(uint4*)&Qh[r * PADA + c8] = *(const uint4*)&g_qh[qoff + r * DD + c8];
        *(uint4*)&Ql[r * PADA + c8] = *(const uint4*)&g_ql[qoff + r * DD + c8];
        *(uint4*)&Kh[r * PADA + c8] = *(const uint4*)&g_kh[koff + r * DD + c8];
        *(uint4*)&Kl[r * PADA + c8] = *(const uint4*)&g_kl[koff + r * DD + c8];
    }
    __syncthreads();

    const int wm = wid >> 1, wn = wid & 1;
    const int m0 = wm * 32, n0 = wn * 64;

    float acc[2][8][4];
#pragma unroll
    for (int i = 0; i < 2; i++)
#pragma unroll
        for (int j = 0; j < 8; j++)
#pragma unroll
            for (int v = 0; v < 4; v++) acc[i][j][v] = 0.0f;

    const uint32_t QhU = smem_u32(Qh), QlU = smem_u32(Ql);
    const uint32_t KhU = smem_u32(Kh), KlU = smem_u32(Kl);
    const int arow = lane & 15, acol8 = (lane >> 4) * 8;

#pragma unroll
    for (int ks = 0; ks < 4; ks++) {
        const int k = ks * 16;
        const uint32_t aoff = (uint32_t)(((m0 + arow) * PADA + k + acol8) * 2);
        const uint32_t boff = (uint32_t)(((n0 + arow) * PADA + k + acol8) * 2);

        uint32_t aQh[2][4], aQl[2][4];
        ldsm4(aQh[0], QhU + aoff);
        ldsm4(aQh[1], QhU + aoff + (uint32_t)(16 * PADA * 2));
        ldsm4(aQl[0], QlU + aoff);
        ldsm4(aQl[1], QlU + aoff + (uint32_t)(16 * PADA * 2));

        uint32_t bKh[4][4], bKl[4][4];
#pragma unroll
        for (int jj = 0; jj < 4; jj++) {
            ldsm4(bKh[jj], KhU + boff + (uint32_t)(jj * 16 * PADA * 2));
            ldsm4(bKl[jj], KlU + boff + (uint32_t)(jj * 16 * PADA * 2));
        }

#pragma unroll
        for (int jj = 0; jj < 4; jj++) {
#pragma unroll
            for (int i = 0; i < 2; i++) {
                mma_bf16(acc[i][2 * jj],     aQh[i], bKh[jj][0], bKh[jj][2]);
                mma_bf16(acc[i][2 * jj + 1], aQh[i], bKh[jj][1], bKh[jj][3]);
                mma_bf16(acc[i][2 * jj],     aQh[i], bKl[jj][0], bKl[jj][2]);
                mma_bf16(acc[i][2 * jj + 1], aQh[i], bKl[jj][1], bKl[jj][3]);
                mma_bf16(acc[i][2 * jj],     aQl[i], bKh[jj][0], bKh[jj][2]);
                mma_bf16(acc[i][2 * jj + 1], aQl[i], bKh[jj][1], bKh[jj][3]);
            }
        }
    }

    // epilogue: e = masked ? 0 : exp2(v*SCL2E), store, row sums
    const int rr = lane >> 2, cc = (lane & 3) * 2;
    const unsigned char* mb = (const unsigned char*)g_maskbits
        + ((size_t)b * SS + q0) * MROWB + ((k0 + n0) >> 3);
#pragma unroll
    for (int i = 0; i < 2; i++) {
        int lrow = m0 + i * 16 + rr;
        int row = q0 + lrow;
        size_t abase = ((size_t)bh * SS + row) * SS + k0 + n0 + cc;
        unsigned long long w0 =
            *(const unsigned long long*)(mb + (size_t)lrow * MROWB);
        unsigned long long w1 =
            *(const unsigned long long*)(mb + (size_t)(lrow + 8) * MROWB);
        float s0 = 0.0f, s1 = 0.0f;
#pragma unroll
        for (int j = 0; j < 8; j++) {
            int pos = cc + j * 8;
            float e0 = ((w0 >> pos) & 1ull)       ? 0.0f : exp2f(acc[i][j][0] * SCL2E);
            float e1 = ((w0 >> (pos + 1)) & 1ull) ? 0.0f : exp2f(acc[i][j][1] * SCL2E);
            float f0 = ((w1 >> pos) & 1ull)       ? 0.0f : exp2f(acc[i][j][2] * SCL2E);
            float f1 = ((w1 >> (pos + 1)) & 1ull) ? 0.0f : exp2f(acc[i][j][3] * SCL2E);
            s0 += e0 + e1;
            s1 += f0 + f1;
            *(float2*)&attn[abase + j * 8]          = make_float2(e0, e1);
            *(float2*)&attn[abase + j * 8 + 8 * SS] = make_float2(f0, f1);
        }
        s0 += __shfl_xor_sync(0xffffffffu, s0, 1);
        s0 += __shfl_xor_sync(0xffffffffu, s0, 2);
        s1 += __shfl_xor_sync(0xffffffffu, s1, 1);
        s1 += __shfl_xor_sync(0xffffffffu, s1, 2);
        if ((lane & 3) == 0) {
            wreds[wn * 128 + lrow]     = s0;
            wreds[wn * 128 + lrow + 8] = s1;
        }
    }
    __syncthreads();

    if (tid < 128)
        g_st[bh][q0 + tid][kt] = wreds[tid] + wreds[128 + tid];
}

// ---------------------------------------------------------------------------
// PV: read e, p = e * sinv[row], write FINAL p, accumulate ctx via MMA.
// CTA 64q x 64n, 32 k-chunks of 64, double-buffered. Combine folded in.
// ---------------------------------------------------------------------------
__global__ __launch_bounds__(256, 2) void pv_kernel(
    float* __restrict__ attn, const float* __restrict__ V,
    float* __restrict__ ctx)
{
    extern __shared__ __align__(16) char smem[];
    float* sinv_s = (float*)(smem + 8 * PLNB);   // [64]

    const int tid = threadIdx.x, lane = tid & 31, wid = tid >> 5;
    const int bh = blockIdx.y;
    const int q0 = blockIdx.x * 64;

    float* Ap = attn + ((size_t)bh * SS + q0) * SS;
    const float* Vp = V + (size_t)bh * SS * DD;

    if (tid < 64) {
        const float* st = g_st[bh][q0 + tid];
        float s = 0.0f;
#pragma unroll
        for (int t = 0; t < NQT; t++) s += st[t];
        sinv_s[tid] = 1.0f / s;
    }
    __syncthreads();

    int lr[4], lc[4];
#pragma unroll
    for (int t = 0; t < 4; t++) {
        int i4 = tid + t * 256;
        lr[t] = i4 >> 4;
        lc[t] = (i4 & 15) * 4;
    }

    const uint32_t sbU = smem_u32(smem);
    const int wm = wid >> 1, wn = wid & 1;
    const int m0 = wm * 16, n0 = wn * 32;
    const int arow = lane & 15, acol8 = (lane >> 4) * 8;

    float acc[4][4];
#pragma unroll
    for (int j = 0; j < 4; j++)
#pragma unroll
        for (int v = 0; v < 4; v++) acc[j][v] = 0.0f;

    float4 pr[4], vr[4];

#pragma unroll
    for (int t = 0; t < 4; t++) {
        pr[t] = *(const float4*)&Ap[(size_t)lr[t] * SS + lc[t]];
        vr[t] = *(const float4*)&Vp[(size_t)lr[t] * DD + lc[t]];
    }
    {
        char* buf = (char*)smem;
#pragma unroll
        for (int t = 0; t < 4; t++) {
            float iv = sinv_s[lr[t]];
            float4 p = make_float4(pr[t].x * iv, pr[t].y * iv,
                                   pr[t].z * iv, pr[t].w * iv);
            *(float4*)&Ap[(size_t)lr[t] * SS + lc[t]] = p;
            uint2 hi, lo;
            split4(p, hi, lo);
            *(uint2*)(buf + (lr[t] * PADA + lc[t]) * 2)        = hi;
            *(uint2*)(buf + PLNB + (lr[t] * PADA + lc[t]) * 2) = lo;
            split4(vr[t], hi, lo);
            *(uint2*)(buf + 2 * PLNB + (lr[t] * PADA + lc[t]) * 2) = hi;
            *(uint2*)(buf + 3 * PLNB + (lr[t] * PADA + lc[t]) * 2) = lo;
        }
    }
    __syncthreads();

    for (int kc = 0; kc < 32; kc++) {
        const int cur = kc & 1;
        if (kc < 31) {
            const int kn = (kc + 1) * 64;
#pragma unroll
            for (int t = 0; t < 4; t++) {
                pr[t] = *(const float4*)&Ap[(size_t)lr[t] * SS + kn + lc[t]];
                vr[t] = *(const float4*)&Vp[(size_t)(kn + lr[t]) * DD + lc[t]];
            }
        }

        const uint32_t bufU = sbU + cur * 4 * PLNB;
        const uint32_t PhU = bufU, PlU = bufU + PLNB;
        const uint32_t VhU = bufU + 2 * PLNB, VlU = bufU + 3 * PLNB;
#pragma unroll
        for (int t = 0; t < 3; t++) {
            uint32_t aT = (t == 2) ? PlU : PhU;
            uint32_t bT = (t == 1) ? VlU : VhU;
#pragma unroll
            for (int ks = 0; ks < 4; ks++) {
                const int kk = ks * 16;
                uint32_t a[4];
                ldsm4(a, aT + (uint32_t)(((m0 + arow) * PADA + kk + acol8) * 2));
                uint32_t bt0[4], bt1[4];
                ldsm4t(bt0, bT + (uint32_t)(((kk + arow) * PADA + n0 + acol8) * 2));
                ldsm4t(bt1, bT + (uint32_t)(((kk + arow) * PADA + n0 + 16 + acol8) * 2));
                mma_bf16(acc[0], a, bt0[0], bt0[1]);
                mma_bf16(acc[1], a, bt0[2], bt0[3]);
                mma_bf16(acc[2], a, bt1[0], bt1[1]);
                mma_bf16(acc[3], a, bt1[2], bt1[3]);
            }
        }

        if (kc < 31) {
            const int kn = (kc + 1) * 64;
            char* buf = (char*)smem + (1 - cur) * 4 * PLNB;
#pragma unroll
            for (int t = 0; t < 4; t++) {
                float iv = sinv_s[lr[t]];
                float4 p = make_float4(pr[t].x * iv, pr[t].y * iv,
                                       pr[t].z * iv, pr[t].w * iv);
                *(float4*)&Ap[(size_t)lr[t] * SS + kn + lc[t]] = p;
                uint2 hi, lo;
                split4(p, hi, lo);
                *(uint2*)(buf + (lr[t] * PADA + lc[t]) * 2)        = hi;
                *(uint2*)(buf + PLNB + (lr[t] * PADA + lc[t]) * 2) = lo;
                split4(vr[t], hi, lo);
                *(uint2*)(buf + 2 * PLNB + (lr[t] * PADA + lc[t]) * 2) = hi;
                *(uint2*)(buf + 3 * PLNB + (lr[t] * PADA + lc[t]) * 2) = lo;
            }
        }
        __syncthreads();
    }

    const int rr = lane >> 2, cc = (lane & 3) * 2;
    const int row = q0 + m0 + rr;
    float* cb = ctx + ((size_t)bh * SS + row) * DD + n0 + cc;
#pragma unroll
    for (int j = 0; j < 4; j++) {
        *(float2*)&cb[j * 8]          = make_float2(acc[j][0], acc[j][1]);
        *(float2*)&cb[j * 8 + 8 * DD] = make_float2(acc[j][2], acc[j][3]);
    }
}

// ---------------------------------------------------------------------------
extern "C" void kernel_launch(void* const* d_in, const int* in_sizes, int n_in,
                              void* d_out, int out_size)
{
    const float* Q = (const float*)d_in[0];
    const float* K = (const float*)d_in[1];
    const float* V = (const float*)d_in[2];
    const void*  M = d_in[3];

    float* out  = (float*)d_out;
    float* ctx  = out;
    float* attn = out + NQK;

    const int QK_SMEM = 4 * 128 * PADA * 2 + 256 * 4;   // 74752
    const int PV_SMEM = 8 * PLNB + 64 * 4;              // 73984

    cudaFuncSetAttribute(qk_mma_kernel,
                         cudaFuncAttributeMaxDynamicSharedMemorySize, QK_SMEM);
    cudaFuncSetAttribute(pv_kernel,
                         cudaFuncAttributeMaxDynamicSharedMemorySize, PV_SMEM);

    probe_mask_kernel<<<1, 32>>>(M);
    prep_mask_kernel<<<(unsigned)((size_t)BB * SS * SS / 32 / 256), 256>>>(M);
    prep_qk_kernel<<<(unsigned)((NQK / 4 + 255) / 256), 256>>>(Q, K);

    dim3 g1(SS / 128, SS / 128, BB * HH);
    qk_mma_kernel<<<g1, 256, QK_SMEM>>>(attn);

    dim3 g3(SS / 64, BB * HH);
    pv_kernel<<<g3, 256, PV_SMEM>>>(attn, V, ctx);
}

// round 12
// speedup vs baseline: 1.0097x; 1.0097x over previous
#include <cuda_runtime.h>
#include <cuda_bf16.h>
#include <cstdint>

#define BB 2
#define HH 16
#define SS 2048
#define DD 64
#define SCL2E 0.1803368801111243f   /* (1/8) * log2(e) */
#define PADA 72
#define NQT 16
#define PLNB (64 * PADA * 2)
#define NQK ((size_t)BB * HH * SS * DD)
#define MROWB (SS / 8)              /* mask bits row stride: 256 bytes */
#define TILEB (4 * 128 * PADA * 2)  /* qk bf16 tiles: 73728 */

__device__ float g_st[BB * HH][SS][NQT];
__device__ int   g_mask_flag;
__device__ __nv_bfloat16 g_qh[NQK], g_ql[NQK], g_kh[NQK], g_kl[NQK];
__device__ unsigned long long g_maskbits[(size_t)BB * SS * SS / 64];   // 1 MB

// ---------------------------------------------------------------------------
__global__ void probe_mask_kernel(const void* m) {
    const unsigned int* w = (const unsigned int*)m;
    int lane = threadIdx.x;
    bool a01 = true, af = true;
    for (int i = lane * 32; i < lane * 32 + 32; i++) {
        unsigned int v = w[i];
        if (v != 0u && v != 1u) a01 = false;
        if (v != 0u && v != 0x3F800000u) af = false;
    }
    unsigned b1 = __ballot_sync(0xffffffffu, a01);
    unsigned b2 = __ballot_sync(0xffffffffu, af);
    if (lane == 0) g_mask_flag = (b1 == 0xffffffffu) ? 0 : ((b2 == 0xffffffffu) ? 1 : 2);
}

// ---------------------------------------------------------------------------
__device__ __forceinline__ uint32_t smem_u32(const void* p) {
    uint32_t a;
    asm("{ .reg .u64 t; cvta.to.shared.u64 t, %1; cvt.u32.u64 %0, t; }"
        : "=r"(a) : "l"(p));
    return a;
}

__device__ __forceinline__ void ldsm4(uint32_t* r, uint32_t addr) {
    asm volatile("ldmatrix.sync.aligned.m8n8.x4.shared.b16 {%0,%1,%2,%3}, [%4];"
                 : "=r"(r[0]), "=r"(r[1]), "=r"(r[2]), "=r"(r[3]) : "r"(addr));
}

__device__ __forceinline__ void ldsm4t(uint32_t* r, uint32_t addr) {
    asm volatile("ldmatrix.sync.aligned.m8n8.x4.trans.shared.b16 {%0,%1,%2,%3}, [%4];"
                 : "=r"(r[0]), "=r"(r[1]), "=r"(r[2]), "=r"(r[3]) : "r"(addr));
}

__device__ __forceinline__ void mma_bf16(float* c, const uint32_t* a,
                                         const uint32_t b0, const uint32_t b1) {
    asm volatile(
        "mma.sync.aligned.m16n8k16.row.col.f32.bf16.bf16.f32 "
        "{%0,%1,%2,%3}, {%4,%5,%6,%7}, {%8,%9}, {%0,%1,%2,%3};"
        : "+f"(c[0]), "+f"(c[1]), "+f"(c[2]), "+f"(c[3])
        : "r"(a[0]), "r"(a[1]), "r"(a[2]), "r"(a[3]), "r"(b0), "r"(b1));
}

__device__ __forceinline__ uint32_t pack2(__nv_bfloat16 a, __nv_bfloat16 b) {
    __nv_bfloat162 t(a, b);
    return *(uint32_t*)&t;
}

__device__ __forceinline__ void split4(float4 v, uint2& hi, uint2& lo) {
    __nv_bfloat16 hx = __float2bfloat16(v.x), hy = __float2bfloat16(v.y);
    __nv_bfloat16 hz = __float2bfloat16(v.z), hw = __float2bfloat16(v.w);
    hi.x = pack2(hx, hy);
    hi.y = pack2(hz, hw);
    lo.x = pack2(__float2bfloat16(v.x - __bfloat162float(hx)),
                 __float2bfloat16(v.y - __bfloat162float(hy)));
    lo.y = pack2(__float2bfloat16(v.z - __bfloat162float(hz)),
                 __float2bfloat16(v.w - __bfloat162float(hw)));
}

// ---------------------------------------------------------------------------
__global__ __launch_bounds__(256) void prep_qk_kernel(
    const float* __restrict__ Q, const float* __restrict__ K)
{
    size_t i4 = ((size_t)blockIdx.x * 256 + threadIdx.x) * 4;
    if (i4 >= NQK) return;
    uint2 hi, lo;
    split4(*(const float4*)&Q[i4], hi, lo);
    *(uint2*)&g_qh[i4] = hi;
    *(uint2*)&g_ql[i4] = lo;
    split4(*(const float4*)&K[i4], hi, lo);
    *(uint2*)&g_kh[i4] = hi;
    *(uint2*)&g_kl[i4] = lo;
}

// ---------------------------------------------------------------------------
__global__ __launch_bounds__(256) void prep_mask_kernel(const void* __restrict__ m)
{
    const int flag = g_mask_flag;
    size_t w32 = (size_t)blockIdx.x * 256 + threadIdx.x;
    if (w32 >= (size_t)BB * SS * SS / 32) return;
    size_t e0 = w32 * 32;
    uint32_t bits = 0;
    if (flag == 2) {
        const unsigned char* mp = (const unsigned char*)m + e0;
#pragma unroll
        for (int q = 0; q < 2; q++) {
            uint4 w = *(const uint4*)&mp[q * 16];
            uint32_t ws[4] = {w.x, w.y, w.z, w.w};
#pragma unroll
            for (int k = 0; k < 4; k++)
#pragma unroll
                for (int bidx = 0; bidx < 4; bidx++)
                    if ((ws[k] >> (bidx * 8)) & 0xFF)
                        bits |= 1u << (q * 16 + k * 4 + bidx);
        }
    } else {
        const int* mp = (const int*)m + e0;
#pragma unroll
        for (int q = 0; q < 8; q++) {
            int4 w = *(const int4*)&mp[q * 4];
            if (w.x) bits |= 1u << (q * 4);
            if (w.y) bits |= 1u << (q * 4 + 1);
            if (w.z) bits |= 1u << (q * 4 + 2);
            if (w.w) bits |= 1u << (q * 4 + 3);
        }
    }
    ((uint32_t*)g_maskbits)[w32] = bits;
}

// ---------------------------------------------------------------------------
// QK: e = exp2(score*SCL2E) (0 where masked) -> attn; row sums -> g_st.
// CTA 128q x 128k; 8 warps 4(m) x 2(n). Mask prefetched at kernel start,
// pre-shifted, staged in smem scratch; epilogue uses static-shift extraction.
// ---------------------------------------------------------------------------
__global__ __launch_bounds__(256, 2) void qk_mma_kernel(float* __restrict__ attn)
{
    extern __shared__ __align__(16) char smem[];
    __nv_bfloat16* Qh = (__nv_bfloat16*)smem;
    __nv_bfloat16* Ql = Qh + 128 * PADA;
    __nv_bfloat16* Kh = Ql + 128 * PADA;
    __nv_bfloat16* Kl = Kh + 128 * PADA;
    float* wreds = (float*)(smem + TILEB);            // [2][128]
    uint32_t* mscr = (uint32_t*)(smem + TILEB + 1024); // [8][256]

    const int tid = threadIdx.x, lane = tid & 31, wid = tid >> 5;
    const int bh = blockIdx.z, b = bh >> 4;
    const int q0 = blockIdx.y * 128, k0 = blockIdx.x * 128;
    const int kt = blockIdx.x;

    const int wm = wid >> 1, wn = wid & 1;
    const int m0 = wm * 32, n0 = wn * 64;
    const int rr = lane >> 2, cc = (lane & 3) * 2;

    // ---- mask prefetch (issued FIRST: longest latency, hidden by tile fill)
    {
        const unsigned char* mb = (const unsigned char*)g_maskbits
            + ((size_t)b * SS + q0) * MROWB + ((k0 + n0) >> 3);
#pragma unroll
        for (int i = 0; i < 2; i++) {
            int lrow = m0 + i * 16 + rr;
            uint2 w0 = *(const uint2*)(mb + (size_t)lrow * MROWB);
            uint2 w1 = *(const uint2*)(mb + (size_t)(lrow + 8) * MROWB);
            // pre-shift by cc: bit for col (cc + j*8) lands at static pos (j&3)*8
            mscr[(i * 4 + 0) * 256 + tid] = w0.x >> cc;
            mscr[(i * 4 + 1) * 256 + tid] = w0.y >> cc;
            mscr[(i * 4 + 2) * 256 + tid] = w1.x >> cc;
            mscr[(i * 4 + 3) * 256 + tid] = w1.y >> cc;
        }
    }

    const size_t qoff = ((size_t)bh * SS + q0) * DD;
    const size_t koff = ((size_t)bh * SS + k0) * DD;
    for (int i8 = tid; i8 < 128 * 8; i8 += 256) {
        int r = i8 >> 3, c8 = (i8 & 7) * 8;
        *(uint4*)&Qh[r * PADA + c8] = *(const uint4*)&g_qh[qoff + r * DD + c8];
        *(uint4*)&Ql[r * PADA + c8] = *(const uint4*)&g_ql[qoff + r * DD + c8];
        *(uint4*)&Kh[r * PADA + c8] = *(const uint4*)&g_kh[koff + r * DD + c8];
        *(uint4*)&Kl[r * PADA + c8] = *(const uint4*)&g_kl[koff + r * DD + c8];
    }
    __syncthreads();

    float acc[2][8][4];
#pragma unroll
    for (int i = 0; i < 2; i++)
#pragma unroll
        for (int j = 0; j < 8; j++)
#pragma unroll
            for (int v = 0; v < 4; v++) acc[i][j][v] = 0.0f;

    const uint32_t QhU = smem_u32(Qh), QlU = smem_u32(Ql);
    const uint32_t KhU = smem_u32(Kh), KlU = smem_u32(Kl);
    const int arow = lane & 15, acol8 = (lane >> 4) * 8;

#pragma unroll
    for (int ks = 0; ks < 4; ks++) {
        const int k = ks * 16;
        const uint32_t aoff = (uint32_t)(((m0 + arow) * PADA + k + acol8) * 2);
        const uint32_t boff = (uint32_t)(((n0 + arow) * PADA + k + acol8) * 2);

        uint32_t aQh[2][4], aQl[2][4];
        ldsm4(aQh[0], QhU + aoff);
        ldsm4(aQh[1], QhU + aoff + (uint32_t)(16 * PADA * 2));
        ldsm4(aQl[0], QlU + aoff);
        ldsm4(aQl[1], QlU + aoff + (uint32_t)(16 * PADA * 2));

        uint32_t bKh[4][4], bKl[4][4];
#pragma unroll
        for (int jj = 0; jj < 4; jj++) {
            ldsm4(bKh[jj], KhU + boff + (uint32_t)(jj * 16 * PADA * 2));
            ldsm4(bKl[jj], KlU + boff + (uint32_t)(jj * 16 * PADA * 2));
        }

#pragma unroll
        for (int jj = 0; jj < 4; jj++) {
#pragma unroll
            for (int i = 0; i < 2; i++) {
                mma_bf16(acc[i][2 * jj],     aQh[i], bKh[jj][0], bKh[jj][2]);
                mma_bf16(acc[i][2 * jj + 1], aQh[i], bKh[jj][1], bKh[jj][3]);
                mma_bf16(acc[i][2 * jj],     aQh[i], bKl[jj][0], bKl[jj][2]);
                mma_bf16(acc[i][2 * jj + 1], aQh[i], bKl[jj][1], bKl[jj][3]);
                mma_bf16(acc[i][2 * jj],     aQl[i], bKh[jj][0], bKh[jj][2]);
                mma_bf16(acc[i][2 * jj + 1], aQl[i], bKh[jj][1], bKh[jj][3]);
            }
        }
    }

    // epilogue: static-shift mask bits from smem scratch
#pragma unroll
    for (int i = 0; i < 2; i++) {
        int lrow = m0 + i * 16 + rr;
        int row = q0 + lrow;
        size_t abase = ((size_t)bh * SS + row) * SS + k0 + n0 + cc;
        uint32_t w0lo = mscr[(i * 4 + 0) * 256 + tid];
        uint32_t w0hi = mscr[(i * 4 + 1) * 256 + tid];
        uint32_t w1lo = mscr[(i * 4 + 2) * 256 + tid];
        uint32_t w1hi = mscr[(i * 4 + 3) * 256 + tid];
        float s0 = 0.0f, s1 = 0.0f;
#pragma unroll
        for (int j = 0; j < 8; j++) {
            uint32_t wa = (j < 4) ? w0lo : w0hi;
            uint32_t wb = (j < 4) ? w1lo : w1hi;
            const int sh = (j & 3) * 8;
            float e0 = ((wa >> sh) & 1u)       ? 0.0f : exp2f(acc[i][j][0] * SCL2E);
            float e1 = ((wa >> (sh + 1)) & 1u) ? 0.0f : exp2f(acc[i][j][1] * SCL2E);
            float f0 = ((wb >> sh) & 1u)       ? 0.0f : exp2f(acc[i][j][2] * SCL2E);
            float f1 = ((wb >> (sh + 1)) & 1u) ? 0.0f : exp2f(acc[i][j][3] * SCL2E);
            s0 += e0 + e1;
            s1 += f0 + f1;
            *(float2*)&attn[abase + j * 8]          = make_float2(e0, e1);
            *(float2*)&attn[abase + j * 8 + 8 * SS] = make_float2(f0, f1);
        }
        s0 += __shfl_xor_sync(0xffffffffu, s0, 1);
        s0 += __shfl_xor_sync(0xffffffffu, s0, 2);
        s1 += __shfl_xor_sync(0xffffffffu, s1, 1);
        s1 += __shfl_xor_sync(0xffffffffu, s1, 2);
        if ((lane & 3) == 0) {
            wreds[wn * 128 + lrow]     = s0;
            wreds[wn * 128 + lrow + 8] = s1;
        }
    }
    __syncthreads();

    if (tid < 128)
        g_st[bh][q0 + tid][kt] = wreds[tid] + wreds[128 + tid];
}

// ---------------------------------------------------------------------------
// PV: read e, p = e * sinv[row], write FINAL p, accumulate ctx via MMA.
// CTA 64q x 64n, 32 k-chunks of 64, double-buffered. Combine folded in.
// ---------------------------------------------------------------------------
__global__ __launch_bounds__(256, 2) void pv_kernel(
    float* __restrict__ attn, const float* __restrict__ V,
    float* __restrict__ ctx)
{
    extern __shared__ __align__(16) char smem[];
    float* sinv_s = (float*)(smem + 8 * PLNB);   // [64]

    const int tid = threadIdx.x, lane = tid & 31, wid = tid >> 5;
    const int bh = blockIdx.y;
    const int q0 = blockIdx.x * 64;

    float* Ap = attn + ((size_t)bh * SS + q0) * SS;
    const float* Vp = V + (size_t)bh * SS * DD;

    if (tid < 64) {
        const float* st = g_st[bh][q0 + tid];
        float s = 0.0f;
#pragma unroll
        for (int t = 0; t < NQT; t++) s += st[t];
        sinv_s[tid] = 1.0f / s;
    }
    __syncthreads();

    int lr[4], lc[4];
#pragma unroll
    for (int t = 0; t < 4; t++) {
        int i4 = tid + t * 256;
        lr[t] = i4 >> 4;
        lc[t] = (i4 & 15) * 4;
    }

    const uint32_t sbU = smem_u32(smem);
    const int wm = wid >> 1, wn = wid & 1;
    const int m0 = wm * 16, n0 = wn * 32;
    const int arow = lane & 15, acol8 = (lane >> 4) * 8;

    float acc[4][4];
#pragma unroll
    for (int j = 0; j < 4; j++)
#pragma unroll
        for (int v = 0; v < 4; v++) acc[j][v] = 0.0f;

    float4 pr[4], vr[4];

#pragma unroll
    for (int t = 0; t < 4; t++) {
        pr[t] = *(const float4*)&Ap[(size_t)lr[t] * SS + lc[t]];
        vr[t] = *(const float4*)&Vp[(size_t)lr[t] * DD + lc[t]];
    }
    {
        char* buf = (char*)smem;
#pragma unroll
        for (int t = 0; t < 4; t++) {
            float iv = sinv_s[lr[t]];
            float4 p = make_float4(pr[t].x * iv, pr[t].y * iv,
                                   pr[t].z * iv, pr[t].w * iv);
            *(float4*)&Ap[(size_t)lr[t] * SS + lc[t]] = p;
            uint2 hi, lo;
            split4(p, hi, lo);
            *(uint2*)(buf + (lr[t] * PADA + lc[t]) * 2)        = hi;
            *(uint2*)(buf + PLNB + (lr[t] * PADA + lc[t]) * 2) = lo;
            split4(vr[t], hi, lo);
            *(uint2*)(buf + 2 * PLNB + (lr[t] * PADA + lc[t]) * 2) = hi;
            *(uint2*)(buf + 3 * PLNB + (lr[t] * PADA + lc[t]) * 2) = lo;
        }
    }
    __syncthreads();

    for (int kc = 0; kc < 32; kc++) {
        const int cur = kc & 1;
        if (kc < 31) {
            const int kn = (kc + 1) * 64;
#pragma unroll
            for (int t = 0; t < 4; t++) {
                pr[t] = *(const float4*)&Ap[(size_t)lr[t] * SS + kn + lc[t]];
                vr[t] = *(const float4*)&Vp[(size_t)(kn + lr[t]) * DD + lc[t]];
            }
        }

        const uint32_t bufU = sbU + cur * 4 * PLNB;
        const uint32_t PhU = bufU, PlU = bufU + PLNB;
        const uint32_t VhU = bufU + 2 * PLNB, VlU = bufU + 3 * PLNB;
#pragma unroll
        for (int t = 0; t < 3; t++) {
            uint32_t aT = (t == 2) ? PlU : PhU;
            uint32_t bT = (t == 1) ? VlU : VhU;
#pragma unroll
            for (int ks = 0; ks < 4; ks++) {
                const int kk = ks * 16;
                uint32_t a[4];
                ldsm4(a, aT + (uint32_t)(((m0 + arow) * PADA + kk + acol8) * 2));
                uint32_t bt0[4], bt1[4];
                ldsm4t(bt0, bT + (uint32_t)(((kk + arow) * PADA + n0 + acol8) * 2));
                ldsm4t(bt1, bT + (uint32_t)(((kk + arow) * PADA + n0 + 16 + acol8) * 2));
                mma_bf16(acc[0], a, bt0[0], bt0[1]);
                mma_bf16(acc[1], a, bt0[2], bt0[3]);
                mma_bf16(acc[2], a, bt1[0], bt1[1]);
                mma_bf16(acc[3], a, bt1[2], bt1[3]);
            }
        }

        if (kc < 31) {
            const int kn = (kc + 1) * 64;
            char* buf = (char*)smem + (1 - cur) * 4 * PLNB;
#pragma unroll
            for (int t = 0; t < 4; t++) {
                float iv = sinv_s[lr[t]];
                float4 p = make_float4(pr[t].x * iv, pr[t].y * iv,
                                       pr[t].z * iv, pr[t].w * iv);
                *(float4*)&Ap[(size_t)lr[t] * SS + kn + lc[t]] = p;
                uint2 hi, lo;
                split4(p, hi, lo);
                *(uint2*)(buf + (lr[t] * PADA + lc[t]) * 2)        = hi;
                *(uint2*)(buf + PLNB + (lr[t] * PADA + lc[t]) * 2) = lo;
                split4(vr[t], hi, lo);
                *(uint2*)(buf + 2 * PLNB + (lr[t] * PADA + lc[t]) * 2) = hi;
                *(uint2*)(buf + 3 * PLNB + (lr[t] * PADA + lc[t]) * 2) = lo;
            }
        }
        __syncthreads();
    }

    const int rr = lane >> 2, cc = (lane & 3) * 2;
    const int row = q0 + m0 + rr;
    float* cb = ctx + ((size_t)bh * SS + row) * DD + n0 + cc;
#pragma unroll
    for (int j = 0; j < 4; j++) {
        *(float2*)&cb[j * 8]          = make_float2(acc[j][0], acc[j][1]);
        *(float2*)&cb[j * 8 + 8 * DD] = make_float2(acc[j][2], acc[j][3]);
    }
}

// ---------------------------------------------------------------------------
extern "C" void kernel_launch(void* const* d_in, const int* in_sizes, int n_in,
                              void* d_out, int out_size)
{
    const float* Q = (const float*)d_in[0];
    const float* K = (const float*)d_in[1];
    const float* V = (const float*)d_in[2];
    const void*  M = d_in[3];

    float* out  = (float*)d_out;
    float* ctx  = out;
    float* attn = out + NQK;

    const int QK_SMEM = TILEB + 1024 + 8 * 256 * 4;   // 82944
    const int PV_SMEM = 8 * PLNB + 64 * 4;            // 73984

    cudaFuncSetAttribute(qk_mma_kernel,
                         cudaFuncAttributeMaxDynamicSharedMemorySize, QK_SMEM);
    cudaFuncSetAttribute(pv_kernel,
                         cudaFuncAttributeMaxDynamicSharedMemorySize, PV_SMEM);

    probe_mask_kernel<<<1, 32>>>(M);
    prep_mask_kernel<<<(unsigned)((size_t)BB * SS * SS / 32 / 256), 256>>>(M);
    prep_qk_kernel<<<(unsigned)((NQK / 4 + 255) / 256), 256>>>(Q, K);

    dim3 g1(SS / 128, SS / 128, BB * HH);
    qk_mma_kernel<<<g1, 256, QK_SMEM>>>(attn);

    dim3 g3(SS / 64, BB * HH);
    pv_kernel<<<g3, 256, PV_SMEM>>>(attn, V, ctx);
}

// round 13
// speedup vs baseline: 1.0993x; 1.0887x over previous
#include <cuda_runtime.h>
#include <cuda_bf16.h>
#include <cstdint>

#define BB 2
#define HH 16
#define SS 2048
#define DD 64
#define SCL2E 0.1803368801111243f   /* (1/8) * log2(e) */
#define PADA 72
#define NQT 16
#define PLNB (64 * PADA * 2)
#define NQK ((size_t)BB * HH * SS * DD)
#define MROWB (SS / 8)              /* mask bits row stride: 256 bytes */
#define QPLN (64 * PADA * 2)        /* qk Q plane bytes: 9216 */
#define KPLN (128 * PADA * 2)       /* qk K plane bytes: 18432 */

__device__ float g_ssum[BB * HH][SS];
__device__ int   g_mask_flag;
__device__ __nv_bfloat16 g_qh[NQK], g_ql[NQK], g_kh[NQK], g_kl[NQK];
__device__ unsigned long long g_maskbits[(size_t)BB * SS * SS / 64];   // 1 MB

// ---------------------------------------------------------------------------
__global__ void probe_mask_kernel(const void* m) {
    uint4 w = ((const uint4*)m)[threadIdx.x];
    bool a01 = (w.x <= 1u) && (w.y <= 1u) && (w.z <= 1u) && (w.w <= 1u);
    auto okf = [](unsigned v) { return v == 0u || v == 0x3F800000u; };
    bool af = okf(w.x) && okf(w.y) && okf(w.z) && okf(w.w);
    int all1 = __syncthreads_and((int)a01);
    int all2 = __syncthreads_and((int)af);
    if (threadIdx.x == 0) g_mask_flag = all1 ? 0 : (all2 ? 1 : 2);
}

// ---------------------------------------------------------------------------
__device__ __forceinline__ uint32_t smem_u32(const void* p) {
    uint32_t a;
    asm("{ .reg .u64 t; cvta.to.shared.u64 t, %1; cvt.u32.u64 %0, t; }"
        : "=r"(a) : "l"(p));
    return a;
}

__device__ __forceinline__ void ldsm4(uint32_t* r, uint32_t addr) {
    asm volatile("ldmatrix.sync.aligned.m8n8.x4.shared.b16 {%0,%1,%2,%3}, [%4];"
                 : "=r"(r[0]), "=r"(r[1]), "=r"(r[2]), "=r"(r[3]) : "r"(addr));
}

__device__ __forceinline__ void ldsm4t(uint32_t* r, uint32_t addr) {
    asm volatile("ldmatrix.sync.aligned.m8n8.x4.trans.shared.b16 {%0,%1,%2,%3}, [%4];"
                 : "=r"(r[0]), "=r"(r[1]), "=r"(r[2]), "=r"(r[3]) : "r"(addr));
}

__device__ __forceinline__ void mma_bf16(float* c, const uint32_t* a,
                                         const uint32_t b0, const uint32_t b1) {
    asm volatile(
        "mma.sync.aligned.m16n8k16.row.col.f32.bf16.bf16.f32 "
        "{%0,%1,%2,%3}, {%4,%5,%6,%7}, {%8,%9}, {%0,%1,%2,%3};"
        : "+f"(c[0]), "+f"(c[1]), "+f"(c[2]), "+f"(c[3])
        : "r"(a[0]), "r"(a[1]), "r"(a[2]), "r"(a[3]), "r"(b0), "r"(b1));
}

#define CPA16(dst, src) \
    asm volatile("cp.async.cg.shared.global [%0], [%1], 16;" \
                 :: "r"(dst), "l"(src) : "memory")
#define CPA_COMMIT() asm volatile("cp.async.commit_group;" ::: "memory")
#define CPA_WAIT0()  asm volatile("cp.async.wait_group 0;" ::: "memory")

__device__ __forceinline__ uint32_t pack2(__nv_bfloat16 a, __nv_bfloat16 b) {
    __nv_bfloat162 t(a, b);
    return *(uint32_t*)&t;
}

__device__ __forceinline__ void split4(float4 v, uint2& hi, uint2& lo) {
    __nv_bfloat16 hx = __float2bfloat16(v.x), hy = __float2bfloat16(v.y);
    __nv_bfloat16 hz = __float2bfloat16(v.z), hw = __float2bfloat16(v.w);
    hi.x = pack2(hx, hy);
    hi.y = pack2(hz, hw);
    lo.x = pack2(__float2bfloat16(v.x - __bfloat162float(hx)),
                 __float2bfloat16(v.y - __bfloat162float(hy)));
    lo.y = pack2(__float2bfloat16(v.z - __bfloat162float(hz)),
                 __float2bfloat16(v.w - __bfloat162float(hw)));
}

// ---------------------------------------------------------------------------
__global__ __launch_bounds__(256) void prep_qk_kernel(
    const float* __restrict__ Q, const float* __restrict__ K)
{
    size_t i4 = ((size_t)blockIdx.x * 256 + threadIdx.x) * 4;
    if (i4 >= NQK) return;
    uint2 hi, lo;
    split4(*(const float4*)&Q[i4], hi, lo);
    *(uint2*)&g_qh[i4] = hi;
    *(uint2*)&g_ql[i4] = lo;
    split4(*(const float4*)&K[i4], hi, lo);
    *(uint2*)&g_kh[i4] = hi;
    *(uint2*)&g_kl[i4] = lo;
}

// ---------------------------------------------------------------------------
__global__ __launch_bounds__(256) void prep_mask_kernel(const void* __restrict__ m)
{
    const int flag = g_mask_flag;
    size_t w32 = (size_t)blockIdx.x * 256 + threadIdx.x;
    if (w32 >= (size_t)BB * SS * SS / 32) return;
    size_t e0 = w32 * 32;
    uint32_t bits = 0;
    if (flag == 2) {
        const unsigned char* mp = (const unsigned char*)m + e0;
#pragma unroll
        for (int q = 0; q < 2; q++) {
            uint4 w = *(const uint4*)&mp[q * 16];
            uint32_t ws[4] = {w.x, w.y, w.z, w.w};
#pragma unroll
            for (int k = 0; k < 4; k++)
#pragma unroll
                for (int bidx = 0; bidx < 4; bidx++)
                    if ((ws[k] >> (bidx * 8)) & 0xFF)
                        bits |= 1u << (q * 16 + k * 4 + bidx);
        }
    } else {
        const int* mp = (const int*)m + e0;
#pragma unroll
        for (int q = 0; q < 8; q++) {
            int4 w = *(const int4*)&mp[q * 4];
            if (w.x) bits |= 1u << (q * 4);
            if (w.y) bits |= 1u << (q * 4 + 1);
            if (w.z) bits |= 1u << (q * 4 + 2);
            if (w.w) bits |= 1u << (q * 4 + 3);
        }
    }
    ((uint32_t*)g_maskbits)[w32] = bits;
}

// ---------------------------------------------------------------------------
// QK pipelined: CTA = 64-q strip, loops 16 k-tiles of 128. Q in smem once;
// K double-buffered via cp.async; mask prefetched to regs one tile ahead.
// e = exp2(score*SCL2E) (0 where masked) -> attn; row sums -> g_ssum (once).
// smem: Qh|Ql (9216 ea) | Kh0|Kl0|Kh1|Kl1 (18432 ea) | wreds 512B = 92672.
// ---------------------------------------------------------------------------
__global__ __launch_bounds__(256, 2) void qk_mma_kernel(float* __restrict__ attn)
{
    extern __shared__ __align__(16) char smem[];
    __nv_bfloat16* Qh = (__nv_bfloat16*)smem;
    __nv_bfloat16* Ql = (__nv_bfloat16*)(smem + QPLN);
    char* kbufs = smem + 2 * QPLN;              // 4 planes of KPLN
    float* wreds = (float*)(smem + 2 * QPLN + 4 * KPLN);   // [2][64]

    const int tid = threadIdx.x, lane = tid & 31, wid = tid >> 5;
    const int bh = blockIdx.y, b = bh >> 4;
    const int q0 = blockIdx.x * 64;

    const int wm = wid >> 1, wn = wid & 1;
    const int m0 = wm * 16, n0 = wn * 64;
    const int rr = lane >> 2, cc = (lane & 3) * 2;
    const int arow = lane & 15, acol8 = (lane >> 4) * 8;

    const size_t qoff = ((size_t)bh * SS + q0) * DD;
    const size_t koff = (size_t)bh * SS * DD;
    const uint32_t kbU = smem_u32(kbufs);

    // per-thread cp.async slots for one K tile (8 x 16B: 4 per plane)
    int krow[4], kcol[4];
#pragma unroll
    for (int p = 0; p < 4; p++) {
        int i8 = tid + p * 256;
        krow[p] = i8 >> 3;
        kcol[p] = (i8 & 7) * 8;
    }

    // K(0) -> buf0 (async)
#pragma unroll
    for (int p = 0; p < 4; p++) {
        uint32_t off = (uint32_t)((krow[p] * PADA + kcol[p]) * 2);
        CPA16(kbU + off,          &g_kh[koff + krow[p] * DD + kcol[p]]);
        CPA16(kbU + KPLN + off,   &g_kl[koff + krow[p] * DD + kcol[p]]);
    }
    CPA_COMMIT();

    // Q -> smem (sync copies; overlap with K(0) in flight)
    for (int i8 = tid; i8 < 64 * 8; i8 += 256) {
        int r = i8 >> 3, c8 = (i8 & 7) * 8;
        *(uint4*)&Qh[r * PADA + c8] = *(const uint4*)&g_qh[qoff + r * DD + c8];
        *(uint4*)&Ql[r * PADA + c8] = *(const uint4*)&g_ql[qoff + r * DD + c8];
    }

    // mask(0) -> regs (pre-shifted by cc)
    const unsigned char* mb = (const unsigned char*)g_maskbits
        + ((size_t)b * SS + q0 + m0 + rr) * MROWB + (n0 >> 3);
    uint32_t m00, m01, m10, m11;
    {
        uint2 a = *(const uint2*)mb;
        uint2 c = *(const uint2*)(mb + 8 * MROWB);
        m00 = a.x >> cc; m01 = a.y >> cc;
        m10 = c.x >> cc; m11 = c.y >> cc;
    }

    CPA_WAIT0();
    __syncthreads();

    const uint32_t QhU = smem_u32(Qh), QlU = smem_u32(Ql);
    float srow0 = 0.0f, srow1 = 0.0f;

    for (int kt = 0; kt < NQT; kt++) {
        const int cur = kt & 1;

        // prefetch K(kt+1) (async) and mask(kt+1) (regs)
        uint32_t n00 = 0, n01 = 0, n10 = 0, n11 = 0;
        if (kt < NQT - 1) {
            const size_t koff2 = koff + (size_t)(kt + 1) * 128 * DD;
            const uint32_t dst = kbU + (uint32_t)((1 - cur) * 2 * KPLN);
#pragma unroll
            for (int p = 0; p < 4; p++) {
                uint32_t off = (uint32_t)((krow[p] * PADA + kcol[p]) * 2);
                CPA16(dst + off,        &g_kh[koff2 + krow[p] * DD + kcol[p]]);
                CPA16(dst + KPLN + off, &g_kl[koff2 + krow[p] * DD + kcol[p]]);
            }
            CPA_COMMIT();
            uint2 a = *(const uint2*)(mb + (kt + 1) * 16);
            uint2 c = *(const uint2*)(mb + (kt + 1) * 16 + 8 * MROWB);
            n00 = a.x >> cc; n01 = a.y >> cc;
            n10 = c.x >> cc; n11 = c.y >> cc;
        }

        // MMA on buf cur
        float acc[8][4];
#pragma unroll
        for (int j = 0; j < 8; j++)
#pragma unroll
            for (int v = 0; v < 4; v++) acc[j][v] = 0.0f;

        const uint32_t KhU = kbU + (uint32_t)(cur * 2 * KPLN);
        const uint32_t KlU = KhU + KPLN;
#pragma unroll
        for (int ks = 0; ks < 4; ks++) {
            const int k = ks * 16;
            uint32_t aQh[4], aQl[4];
            ldsm4(aQh, QhU + (uint32_t)(((m0 + arow) * PADA + k + acol8) * 2));
            ldsm4(aQl, QlU + (uint32_t)(((m0 + arow) * PADA + k + acol8) * 2));
            uint32_t bKh[4][4], bKl[4][4];
#pragma unroll
            for (int jj = 0; jj < 4; jj++) {
                uint32_t boff = (uint32_t)(((n0 + jj * 16 + arow) * PADA
                                            + k + acol8) * 2);
                ldsm4(bKh[jj], KhU + boff);
                ldsm4(bKl[jj], KlU + boff);
            }
#pragma unroll
            for (int jj = 0; jj < 4; jj++) {
                mma_bf16(acc[2 * jj],     aQh, bKh[jj][0], bKh[jj][2]);
                mma_bf16(acc[2 * jj + 1], aQh, bKh[jj][1], bKh[jj][3]);
                mma_bf16(acc[2 * jj],     aQh, bKl[jj][0], bKl[jj][2]);
                mma_bf16(acc[2 * jj + 1], aQh, bKl[jj][1], bKl[jj][3]);
                mma_bf16(acc[2 * jj],     aQl, bKh[jj][0], bKh[jj][2]);
                mma_bf16(acc[2 * jj + 1], aQl, bKh[jj][1], bKh[jj][3]);
            }
        }

        // epilogue: e = masked ? 0 : exp2(v*SCL2E); store; accumulate sums
        size_t abase = ((size_t)bh * SS + q0 + m0 + rr) * SS
                       + (size_t)kt * 128 + n0 + cc;
#pragma unroll
        for (int j = 0; j < 8; j++) {
            uint32_t wa = (j < 4) ? m00 : m01;
            uint32_t wb = (j < 4) ? m10 : m11;
            const int sh = (j & 3) * 8;
            float e0 = ((wa >> sh) & 1u)       ? 0.0f : exp2f(acc[j][0] * SCL2E);
            float e1 = ((wa >> (sh + 1)) & 1u) ? 0.0f : exp2f(acc[j][1] * SCL2E);
            float f0 = ((wb >> sh) & 1u)       ? 0.0f : exp2f(acc[j][2] * SCL2E);
            float f1 = ((wb >> (sh + 1)) & 1u) ? 0.0f : exp2f(acc[j][3] * SCL2E);
            srow0 += e0 + e1;
            srow1 += f0 + f1;
            *(float2*)&attn[abase + j * 8]          = make_float2(e0, e1);
            *(float2*)&attn[abase + j * 8 + 8 * SS] = make_float2(f0, f1);
        }

        if (kt < NQT - 1) CPA_WAIT0();
        __syncthreads();
        m00 = n00; m01 = n01; m10 = n10; m11 = n11;
    }

    // final row-sum reduction -> g_ssum
    srow0 += __shfl_xor_sync(0xffffffffu, srow0, 1);
    srow0 += __shfl_xor_sync(0xffffffffu, srow0, 2);
    srow1 += __shfl_xor_sync(0xffffffffu, srow1, 1);
    srow1 += __shfl_xor_sync(0xffffffffu, srow1, 2);
    if ((lane & 3) == 0) {
        wreds[wn * 64 + m0 + rr]     = srow0;
        wreds[wn * 64 + m0 + 8 + rr] = srow1;
    }
    __syncthreads();
    if (tid < 64)
        g_ssum[bh][q0 + tid] = wreds[tid] + wreds[64 + tid];
}

// ---------------------------------------------------------------------------
// PV: read e, p = e * sinv[row], write FINAL p, accumulate ctx via MMA.
// CTA 64q x 64n, 32 k-chunks of 64, double-buffered.
// ---------------------------------------------------------------------------
__global__ __launch_bounds__(256, 2) void pv_kernel(
    float* __restrict__ attn, const float* __restrict__ V,
    float* __restrict__ ctx)
{
    extern __shared__ __align__(16) char smem[];
    float* sinv_s = (float*)(smem + 8 * PLNB);   // [64]

    const int tid = threadIdx.x, lane = tid & 31, wid = tid >> 5;
    const int bh = blockIdx.y;
    const int q0 = blockIdx.x * 64;

    float* Ap = attn + ((size_t)bh * SS + q0) * SS;
    const float* Vp = V + (size_t)bh * SS * DD;

    if (tid < 64) sinv_s[tid] = 1.0f / g_ssum[bh][q0 + tid];
    __syncthreads();

    int lr[4], lc[4];
#pragma unroll
    for (int t = 0; t < 4; t++) {
        int i4 = tid + t * 256;
        lr[t] = i4 >> 4;
        lc[t] = (i4 & 15) * 4;
    }

    const uint32_t sbU = smem_u32(smem);
    const int wm = wid >> 1, wn = wid & 1;
    const int m0 = wm * 16, n0 = wn * 32;
    const int arow = lane & 15, acol8 = (lane >> 4) * 8;

    float acc[4][4];
#pragma unroll
    for (int j = 0; j < 4; j++)
#pragma unroll
        for (int v = 0; v < 4; v++) acc[j][v] = 0.0f;

    float4 pr[4], vr[4];

#pragma unroll
    for (int t = 0; t < 4; t++) {
        pr[t] = *(const float4*)&Ap[(size_t)lr[t] * SS + lc[t]];
        vr[t] = *(const float4*)&Vp[(size_t)lr[t] * DD + lc[t]];
    }
    {
        char* buf = (char*)smem;
#pragma unroll
        for (int t = 0; t < 4; t++) {
            float iv = sinv_s[lr[t]];
            float4 p = make_float4(pr[t].x * iv, pr[t].y * iv,
                                   pr[t].z * iv, pr[t].w * iv);
            *(float4*)&Ap[(size_t)lr[t] * SS + lc[t]] = p;
            uint2 hi, lo;
            split4(p, hi, lo);
            *(uint2*)(buf + (lr[t] * PADA + lc[t]) * 2)        = hi;
            *(uint2*)(buf + PLNB + (lr[t] * PADA + lc[t]) * 2) = lo;
            split4(vr[t], hi, lo);
            *(uint2*)(buf + 2 * PLNB + (lr[t] * PADA + lc[t]) * 2) = hi;
            *(uint2*)(buf + 3 * PLNB + (lr[t] * PADA + lc[t]) * 2) = lo;
        }
    }
    __syncthreads();

    for (int kc = 0; kc < 32; kc++) {
        const int cur = kc & 1;
        if (kc < 31) {
            const int kn = (kc + 1) * 64;
#pragma unroll
            for (int t = 0; t < 4; t++) {
                pr[t] = *(const float4*)&Ap[(size_t)lr[t] * SS + kn + lc[t]];
                vr[t] = *(const float4*)&Vp[(size_t)(kn + lr[t]) * DD + lc[t]];
            }
        }

        const uint32_t bufU = sbU + cur * 4 * PLNB;
        const uint32_t PhU = bufU, PlU = bufU + PLNB;
        const uint32_t VhU = bufU + 2 * PLNB, VlU = bufU + 3 * PLNB;
#pragma unroll
        for (int t = 0; t < 3; t++) {
            uint32_t aT = (t == 2) ? PlU : PhU;
            uint32_t bT = (t == 1) ? VlU : VhU;
#pragma unroll
            for (int ks = 0; ks < 4; ks++) {
                const int kk = ks * 16;
                uint32_t a[4];
                ldsm4(a, aT + (uint32_t)(((m0 + arow) * PADA + kk + acol8) * 2));
                uint32_t bt0[4], bt1[4];
                ldsm4t(bt0, bT + (uint32_t)(((kk + arow) * PADA + n0 + acol8) * 2));
                ldsm4t(bt1, bT + (uint32_t)(((kk + arow) * PADA + n0 + 16 + acol8) * 2));
                mma_bf16(acc[0], a, bt0[0], bt0[1]);
                mma_bf16(acc[1], a, bt0[2], bt0[3]);
                mma_bf16(acc[2], a, bt1[0], bt1[1]);
                mma_bf16(acc[3], a, bt1[2], bt1[3]);
            }
        }

        if (kc < 31) {
            const int kn = (kc + 1) * 64;
            char* buf = (char*)smem + (1 - cur) * 4 * PLNB;
#pragma unroll
            for (int t = 0; t < 4; t++) {
                float iv = sinv_s[lr[t]];
                float4 p = make_float4(pr[t].x * iv, pr[t].y * iv,
                                       pr[t].z * iv, pr[t].w * iv);
                *(float4*)&Ap[(size_t)lr[t] * SS + kn + lc[t]] = p;
                uint2 hi, lo;
                split4(p, hi, lo);
                *(uint2*)(buf + (lr[t] * PADA + lc[t]) * 2)        = hi;
                *(uint2*)(buf + PLNB + (lr[t] * PADA + lc[t]) * 2) = lo;
                split4(vr[t], hi, lo);
                *(uint2*)(buf + 2 * PLNB + (lr[t] * PADA + lc[t]) * 2) = hi;
                *(uint2*)(buf + 3 * PLNB + (lr[t] * PADA + lc[t]) * 2) = lo;
            }
        }
        __syncthreads();
    }

    const int rr = lane >> 2, cc = (lane & 3) * 2;
    const int row = q0 + m0 + rr;
    float* cb = ctx + ((size_t)bh * SS + row) * DD + n0 + cc;
#pragma unroll
    for (int j = 0; j < 4; j++) {
        *(float2*)&cb[j * 8]          = make_float2(acc[j][0], acc[j][1]);
        *(float2*)&cb[j * 8 + 8 * DD] = make_float2(acc[j][2], acc[j][3]);
    }
}

// ---------------------------------------------------------------------------
extern "C" void kernel_launch(void* const* d_in, const int* in_sizes, int n_in,
                              void* d_out, int out_size)
{
    const float* Q = (const float*)d_in[0];
    const float* K = (const float*)d_in[1];
    const float* V = (const float*)d_in[2];
    const void*  M = d_in[3];

    float* out  = (float*)d_out;
    float* ctx  = out;
    float* attn = out + NQK;

    const int QK_SMEM = 2 * QPLN + 4 * KPLN + 512;   // 92672
    const int PV_SMEM = 8 * PLNB + 64 * 4;           // 73984

    cudaFuncSetAttribute(qk_mma_kernel,
                         cudaFuncAttributeMaxDynamicSharedMemorySize, QK_SMEM);
    cudaFuncSetAttribute(pv_kernel,
                         cudaFuncAttributeMaxDynamicSharedMemorySize, PV_SMEM);

    probe_mask_kernel<<<1, 256>>>(M);
    prep_mask_kernel<<<(unsigned)((size_t)BB * SS * SS / 32 / 256), 256>>>(M);
    prep_qk_kernel<<<(unsigned)((NQK / 4 + 255) / 256), 256>>>(Q, K);

    dim3 g1(SS / 64, BB * HH);
    qk_mma_kernel<<<g1, 256, QK_SMEM>>>(attn);

    dim3 g3(SS / 64, BB * HH);
    pv_kernel<<<g3, 256, PV_SMEM>>>(attn, V, ctx);
}

// round 14
// speedup vs baseline: 1.1022x; 1.0027x over previous
#include <cuda_runtime.h>
#include <cuda_bf16.h>
#include <cstdint>

#define BB 2
#define HH 16
#define SS 2048
#define DD 64
#define SCL2E 0.1803368801111243f   /* (1/8) * log2(e) */
#define PADA 72
#define NQT 16
#define PLNB (64 * PADA * 2)        /* 9216 */
#define NQK ((size_t)BB * HH * SS * DD)
#define MROWB (SS / 8)              /* mask bits row stride: 256 bytes */
#define QPLN (64 * PADA * 2)        /* 9216 */
#define KPLN (128 * PADA * 2)       /* 18432 */
/* fused smem layout:
   [0 .. 2*QPLN)                 Q planes (QK) / P+V pipeline bufs (PV)
   [2*QPLN .. 2*QPLN+4*KPLN)     K double buffers (QK) / PV bufs overflow
   [92160 .. 92672)              wreds [2][64]
   [92672 .. 92928)              sinv  [64]                               */
#define WREDS_OFF (2 * QPLN + 4 * KPLN)
#define SINV_OFF  (WREDS_OFF + 512)
#define FUSED_SMEM (SINV_OFF + 256)

__device__ int g_mask_flag;
__device__ __nv_bfloat16 g_qh[NQK], g_ql[NQK], g_kh[NQK], g_kl[NQK];
__device__ unsigned long long g_maskbits[(size_t)BB * SS * SS / 64];

// ---------------------------------------------------------------------------
__global__ void probe_mask_kernel(const void* m) {
    uint4 w = ((const uint4*)m)[threadIdx.x];
    bool a01 = (w.x <= 1u) && (w.y <= 1u) && (w.z <= 1u) && (w.w <= 1u);
    auto okf = [](unsigned v) { return v == 0u || v == 0x3F800000u; };
    bool af = okf(w.x) && okf(w.y) && okf(w.z) && okf(w.w);
    int all1 = __syncthreads_and((int)a01);
    int all2 = __syncthreads_and((int)af);
    if (threadIdx.x == 0) g_mask_flag = all1 ? 0 : (all2 ? 1 : 2);
}

// ---------------------------------------------------------------------------
__device__ __forceinline__ uint32_t smem_u32(const void* p) {
    uint32_t a;
    asm("{ .reg .u64 t; cvta.to.shared.u64 t, %1; cvt.u32.u64 %0, t; }"
        : "=r"(a) : "l"(p));
    return a;
}

__device__ __forceinline__ void ldsm4(uint32_t* r, uint32_t addr) {
    asm volatile("ldmatrix.sync.aligned.m8n8.x4.shared.b16 {%0,%1,%2,%3}, [%4];"
                 : "=r"(r[0]), "=r"(r[1]), "=r"(r[2]), "=r"(r[3]) : "r"(addr));
}

__device__ __forceinline__ void ldsm4t(uint32_t* r, uint32_t addr) {
    asm volatile("ldmatrix.sync.aligned.m8n8.x4.trans.shared.b16 {%0,%1,%2,%3}, [%4];"
                 : "=r"(r[0]), "=r"(r[1]), "=r"(r[2]), "=r"(r[3]) : "r"(addr));
}

__device__ __forceinline__ void mma_bf16(float* c, const uint32_t* a,
                                         const uint32_t b0, const uint32_t b1) {
    asm volatile(
        "mma.sync.aligned.m16n8k16.row.col.f32.bf16.bf16.f32 "
        "{%0,%1,%2,%3}, {%4,%5,%6,%7}, {%8,%9}, {%0,%1,%2,%3};"
        : "+f"(c[0]), "+f"(c[1]), "+f"(c[2]), "+f"(c[3])
        : "r"(a[0]), "r"(a[1]), "r"(a[2]), "r"(a[3]), "r"(b0), "r"(b1));
}

#define CPA16(dst, src) \
    asm volatile("cp.async.cg.shared.global [%0], [%1], 16;" \
                 :: "r"(dst), "l"(src) : "memory")
#define CPA_COMMIT() asm volatile("cp.async.commit_group;" ::: "memory")
#define CPA_WAIT0()  asm volatile("cp.async.wait_group 0;" ::: "memory")

__device__ __forceinline__ uint32_t pack2(__nv_bfloat16 a, __nv_bfloat16 b) {
    __nv_bfloat162 t(a, b);
    return *(uint32_t*)&t;
}

__device__ __forceinline__ void split4(float4 v, uint2& hi, uint2& lo) {
    __nv_bfloat16 hx = __float2bfloat16(v.x), hy = __float2bfloat16(v.y);
    __nv_bfloat16 hz = __float2bfloat16(v.z), hw = __float2bfloat16(v.w);
    hi.x = pack2(hx, hy);
    hi.y = pack2(hz, hw);
    lo.x = pack2(__float2bfloat16(v.x - __bfloat162float(hx)),
                 __float2bfloat16(v.y - __bfloat162float(hy)));
    lo.y = pack2(__float2bfloat16(v.z - __bfloat162float(hz)),
                 __float2bfloat16(v.w - __bfloat162float(hw)));
}

// ---------------------------------------------------------------------------
__global__ __launch_bounds__(256) void prep_qk_kernel(
    const float* __restrict__ Q, const float* __restrict__ K)
{
    size_t i4 = ((size_t)blockIdx.x * 256 + threadIdx.x) * 4;
    if (i4 >= NQK) return;
    uint2 hi, lo;
    split4(*(const float4*)&Q[i4], hi, lo);
    *(uint2*)&g_qh[i4] = hi;
    *(uint2*)&g_ql[i4] = lo;
    split4(*(const float4*)&K[i4], hi, lo);
    *(uint2*)&g_kh[i4] = hi;
    *(uint2*)&g_kl[i4] = lo;
}

// ---------------------------------------------------------------------------
__global__ __launch_bounds__(256) void prep_mask_kernel(const void* __restrict__ m)
{
    const int flag = g_mask_flag;
    size_t w32 = (size_t)blockIdx.x * 256 + threadIdx.x;
    if (w32 >= (size_t)BB * SS * SS / 32) return;
    size_t e0 = w32 * 32;
    uint32_t bits = 0;
    if (flag == 2) {
        const unsigned char* mp = (const unsigned char*)m + e0;
#pragma unroll
        for (int q = 0; q < 2; q++) {
            uint4 w = *(const uint4*)&mp[q * 16];
            uint32_t ws[4] = {w.x, w.y, w.z, w.w};
#pragma unroll
            for (int k = 0; k < 4; k++)
#pragma unroll
                for (int bidx = 0; bidx < 4; bidx++)
                    if ((ws[k] >> (bidx * 8)) & 0xFF)
                        bits |= 1u << (q * 16 + k * 4 + bidx);
        }
    } else {
        const int* mp = (const int*)m + e0;
#pragma unroll
        for (int q = 0; q < 8; q++) {
            int4 w = *(const int4*)&mp[q * 4];
            if (w.x) bits |= 1u << (q * 4);
            if (w.y) bits |= 1u << (q * 4 + 1);
            if (w.z) bits |= 1u << (q * 4 + 2);
            if (w.w) bits |= 1u << (q * 4 + 3);
        }
    }
    ((uint32_t*)g_maskbits)[w32] = bits;
}

// ---------------------------------------------------------------------------
// FUSED attention kernel. CTA = 64-q strip.
// Phase 1 (QK): loop 16 k-tiles of 128, pipelined K via cp.async; write
//   e = exp2(score*SCL2E)*(mask?0:1) to attn; row sums in registers.
// Transition: reduce sums -> sinv in smem.
// Phase 2 (PV): loop 32 k-chunks of 64; read e (L2-warm), p = e*sinv,
//   write FINAL p in place, accumulate ctx via MMA. Double-buffered.
// ---------------------------------------------------------------------------
__global__ __launch_bounds__(256, 2) void fused_attn_kernel(
    float* __restrict__ attn, const float* __restrict__ V,
    float* __restrict__ ctx)
{
    extern __shared__ __align__(16) char smem[];
    float* wreds  = (float*)(smem + WREDS_OFF);   // [2][64]
    float* sinv_s = (float*)(smem + SINV_OFF);    // [64]

    const int tid = threadIdx.x, lane = tid & 31, wid = tid >> 5;
    const int bh = blockIdx.y, b = bh >> 4;
    const int q0 = blockIdx.x * 64;

    const int rr = lane >> 2, cc = (lane & 3) * 2;
    const int arow = lane & 15, acol8 = (lane >> 4) * 8;

    // =========================== PHASE 1: QK ================================
    {
        __nv_bfloat16* Qh = (__nv_bfloat16*)smem;
        __nv_bfloat16* Ql = (__nv_bfloat16*)(smem + QPLN);
        char* kbufs = smem + 2 * QPLN;
        const int wm = wid >> 1, wn = wid & 1;
        const int m0 = wm * 16, n0 = wn * 64;

        const size_t qoff = ((size_t)bh * SS + q0) * DD;
        const size_t koff = (size_t)bh * SS * DD;
        const uint32_t kbU = smem_u32(kbufs);

        int krow[4], kcol[4];
#pragma unroll
        for (int p = 0; p < 4; p++) {
            int i8 = tid + p * 256;
            krow[p] = i8 >> 3;
            kcol[p] = (i8 & 7) * 8;
        }

        // K(0) async
#pragma unroll
        for (int p = 0; p < 4; p++) {
            uint32_t off = (uint32_t)((krow[p] * PADA + kcol[p]) * 2);
            CPA16(kbU + off,        &g_kh[koff + krow[p] * DD + kcol[p]]);
            CPA16(kbU + KPLN + off, &g_kl[koff + krow[p] * DD + kcol[p]]);
        }
        CPA_COMMIT();

        // Q -> smem
        for (int i8 = tid; i8 < 64 * 8; i8 += 256) {
            int r = i8 >> 3, c8 = (i8 & 7) * 8;
            *(uint4*)&Qh[r * PADA + c8] = *(const uint4*)&g_qh[qoff + r * DD + c8];
            *(uint4*)&Ql[r * PADA + c8] = *(const uint4*)&g_ql[qoff + r * DD + c8];
        }

        // mask(0)
        const unsigned char* mb = (const unsigned char*)g_maskbits
            + ((size_t)b * SS + q0 + m0 + rr) * MROWB + (n0 >> 3);
        uint32_t m00, m01, m10, m11;
        {
            uint2 a = *(const uint2*)mb;
            uint2 c = *(const uint2*)(mb + 8 * MROWB);
            m00 = a.x >> cc; m01 = a.y >> cc;
            m10 = c.x >> cc; m11 = c.y >> cc;
        }

        CPA_WAIT0();
        __syncthreads();

        const uint32_t QhU = smem_u32(Qh), QlU = smem_u32(Ql);
        float srow0 = 0.0f, srow1 = 0.0f;

        for (int kt = 0; kt < NQT; kt++) {
            const int cur = kt & 1;

            uint32_t n00 = 0, n01 = 0, n10 = 0, n11 = 0;
            if (kt < NQT - 1) {
                const size_t koff2 = koff + (size_t)(kt + 1) * 128 * DD;
                const uint32_t dst = kbU + (uint32_t)((1 - cur) * 2 * KPLN);
#pragma unroll
                for (int p = 0; p < 4; p++) {
                    uint32_t off = (uint32_t)((krow[p] * PADA + kcol[p]) * 2);
                    CPA16(dst + off,        &g_kh[koff2 + krow[p] * DD + kcol[p]]);
                    CPA16(dst + KPLN + off, &g_kl[koff2 + krow[p] * DD + kcol[p]]);
                }
                CPA_COMMIT();
                uint2 a = *(const uint2*)(mb + (kt + 1) * 16);
                uint2 c = *(const uint2*)(mb + (kt + 1) * 16 + 8 * MROWB);
                n00 = a.x >> cc; n01 = a.y >> cc;
                n10 = c.x >> cc; n11 = c.y >> cc;
            }

            float acc[8][4];
#pragma unroll
            for (int j = 0; j < 8; j++)
#pragma unroll
                for (int v = 0; v < 4; v++) acc[j][v] = 0.0f;

            const uint32_t KhU = kbU + (uint32_t)(cur * 2 * KPLN);
            const uint32_t KlU = KhU + KPLN;
#pragma unroll
            for (int ks = 0; ks < 4; ks++) {
                const int k = ks * 16;
                uint32_t aQh[4], aQl[4];
                ldsm4(aQh, QhU + (uint32_t)(((m0 + arow) * PADA + k + acol8) * 2));
                ldsm4(aQl, QlU + (uint32_t)(((m0 + arow) * PADA + k + acol8) * 2));
                uint32_t bKh[4][4], bKl[4][4];
#pragma unroll
                for (int jj = 0; jj < 4; jj++) {
                    uint32_t boff = (uint32_t)(((n0 + jj * 16 + arow) * PADA
                                                + k + acol8) * 2);
                    ldsm4(bKh[jj], KhU + boff);
                    ldsm4(bKl[jj], KlU + boff);
                }
#pragma unroll
                for (int jj = 0; jj < 4; jj++) {
                    mma_bf16(acc[2 * jj],     aQh, bKh[jj][0], bKh[jj][2]);
                    mma_bf16(acc[2 * jj + 1], aQh, bKh[jj][1], bKh[jj][3]);
                    mma_bf16(acc[2 * jj],     aQh, bKl[jj][0], bKl[jj][2]);
                    mma_bf16(acc[2 * jj + 1], aQh, bKl[jj][1], bKl[jj][3]);
                    mma_bf16(acc[2 * jj],     aQl, bKh[jj][0], bKh[jj][2]);
                    mma_bf16(acc[2 * jj + 1], aQl, bKh[jj][1], bKh[jj][3]);
                }
            }

            size_t abase = ((size_t)bh * SS + q0 + m0 + rr) * SS
                           + (size_t)kt * 128 + n0 + cc;
#pragma unroll
            for (int j = 0; j < 8; j++) {
                uint32_t wa = (j < 4) ? m00 : m01;
                uint32_t wb = (j < 4) ? m10 : m11;
                const int sh = (j & 3) * 8;
                float e0 = ((wa >> sh) & 1u)       ? 0.0f : exp2f(acc[j][0] * SCL2E);
                float e1 = ((wa >> (sh + 1)) & 1u) ? 0.0f : exp2f(acc[j][1] * SCL2E);
                float f0 = ((wb >> sh) & 1u)       ? 0.0f : exp2f(acc[j][2] * SCL2E);
                float f1 = ((wb >> (sh + 1)) & 1u) ? 0.0f : exp2f(acc[j][3] * SCL2E);
                srow0 += e0 + e1;
                srow1 += f0 + f1;
                *(float2*)&attn[abase + j * 8]          = make_float2(e0, e1);
                *(float2*)&attn[abase + j * 8 + 8 * SS] = make_float2(f0, f1);
            }

            if (kt < NQT - 1) CPA_WAIT0();
            __syncthreads();
            m00 = n00; m01 = n01; m10 = n10; m11 = n11;
        }

        // row sums -> sinv
        srow0 += __shfl_xor_sync(0xffffffffu, srow0, 1);
        srow0 += __shfl_xor_sync(0xffffffffu, srow0, 2);
        srow1 += __shfl_xor_sync(0xffffffffu, srow1, 1);
        srow1 += __shfl_xor_sync(0xffffffffu, srow1, 2);
        if ((lane & 3) == 0) {
            wreds[wn * 64 + m0 + rr]     = srow0;
            wreds[wn * 64 + m0 + 8 + rr] = srow1;
        }
        __syncthreads();
        if (tid < 64)
            sinv_s[tid] = 1.0f / (wreds[tid] + wreds[64 + tid]);
        __syncthreads();
    }

    // =========================== PHASE 2: PV ================================
    {
        float* Ap = attn + ((size_t)bh * SS + q0) * SS;
        const float* Vp = V + (size_t)bh * SS * DD;

        int lr[4], lc[4];
#pragma unroll
        for (int t = 0; t < 4; t++) {
            int i4 = tid + t * 256;
            lr[t] = i4 >> 4;
            lc[t] = (i4 & 15) * 4;
        }

        const uint32_t sbU = smem_u32(smem);
        const int wm = wid >> 1, wn = wid & 1;
        const int m0 = wm * 16, n0 = wn * 32;

        float acc[4][4];
#pragma unroll
        for (int j = 0; j < 4; j++)
#pragma unroll
            for (int v = 0; v < 4; v++) acc[j][v] = 0.0f;

        float4 pr[4], vr[4];

#pragma unroll
        for (int t = 0; t < 4; t++) {
            pr[t] = *(const float4*)&Ap[(size_t)lr[t] * SS + lc[t]];
            vr[t] = *(const float4*)&Vp[(size_t)lr[t] * DD + lc[t]];
        }
        {
            char* buf = (char*)smem;
#pragma unroll
            for (int t = 0; t < 4; t++) {
                float iv = sinv_s[lr[t]];
                float4 p = make_float4(pr[t].x * iv, pr[t].y * iv,
                                       pr[t].z * iv, pr[t].w * iv);
                *(float4*)&Ap[(size_t)lr[t] * SS + lc[t]] = p;
                uint2 hi, lo;
                split4(p, hi, lo);
                *(uint2*)(buf + (lr[t] * PADA + lc[t]) * 2)        = hi;
                *(uint2*)(buf + PLNB + (lr[t] * PADA + lc[t]) * 2) = lo;
                split4(vr[t], hi, lo);
                *(uint2*)(buf + 2 * PLNB + (lr[t] * PADA + lc[t]) * 2) = hi;
                *(uint2*)(buf + 3 * PLNB + (lr[t] * PADA + lc[t]) * 2) = lo;
            }
        }
        __syncthreads();

        for (int kc = 0; kc < 32; kc++) {
            const int cur = kc & 1;
            if (kc < 31) {
                const int kn = (kc + 1) * 64;
#pragma unroll
                for (int t = 0; t < 4; t++) {
                    pr[t] = *(const float4*)&Ap[(size_t)lr[t] * SS + kn + lc[t]];
                    vr[t] = *(const float4*)&Vp[(size_t)(kn + lr[t]) * DD + lc[t]];
                }
            }

            const uint32_t bufU = sbU + cur * 4 * PLNB;
            const uint32_t PhU = bufU, PlU = bufU + PLNB;
            const uint32_t VhU = bufU + 2 * PLNB, VlU = bufU + 3 * PLNB;
#pragma unroll
            for (int t = 0; t < 3; t++) {
                uint32_t aT = (t == 2) ? PlU : PhU;
                uint32_t bT = (t == 1) ? VlU : VhU;
#pragma unroll
                for (int ks = 0; ks < 4; ks++) {
                    const int kk = ks * 16;
                    uint32_t a[4];
                    ldsm4(a, aT + (uint32_t)(((m0 + arow) * PADA + kk + acol8) * 2));
                    uint32_t bt0[4], bt1[4];
                    ldsm4t(bt0, bT + (uint32_t)(((kk + arow) * PADA + n0 + acol8) * 2));
                    ldsm4t(bt1, bT + (uint32_t)(((kk + arow) * PADA + n0 + 16 + acol8) * 2));
                    mma_bf16(acc[0], a, bt0[0], bt0[1]);
                    mma_bf16(acc[1], a, bt0[2], bt0[3]);
                    mma_bf16(acc[2], a, bt1[0], bt1[1]);
                    mma_bf16(acc[3], a, bt1[2], bt1[3]);
                }
            }

            if (kc < 31) {
                const int kn = (kc + 1) * 64;
                char* buf = (char*)smem + (1 - cur) * 4 * PLNB;
#pragma unroll
                for (int t = 0; t < 4; t++) {
                    float iv = sinv_s[lr[t]];
                    float4 p = make_float4(pr[t].x * iv, pr[t].y * iv,
                                           pr[t].z * iv, pr[t].w * iv);
                    *(float4*)&Ap[(size_t)lr[t] * SS + kn + lc[t]] = p;
                    uint2 hi, lo;
                    split4(p, hi, lo);
                    *(uint2*)(buf + (lr[t] * PADA + lc[t]) * 2)        = hi;
                    *(uint2*)(buf + PLNB + (lr[t] * PADA + lc[t]) * 2) = lo;
                    split4(vr[t], hi, lo);
                    *(uint2*)(buf + 2 * PLNB + (lr[t] * PADA + lc[t]) * 2) = hi;
                    *(uint2*)(buf + 3 * PLNB + (lr[t] * PADA + lc[t]) * 2) = lo;
                }
            }
            __syncthreads();
        }

        const int row = q0 + m0 + rr;
        float* cb = ctx + ((size_t)bh * SS + row) * DD + n0 + cc;
#pragma unroll
        for (int j = 0; j < 4; j++) {
            *(float2*)&cb[j * 8]          = make_float2(acc[j][0], acc[j][1]);
            *(float2*)&cb[j * 8 + 8 * DD] = make_float2(acc[j][2], acc[j][3]);
        }
    }
}

// ---------------------------------------------------------------------------
extern "C" void kernel_launch(void* const* d_in, const int* in_sizes, int n_in,
                              void* d_out, int out_size)
{
    const float* Q = (const float*)d_in[0];
    const float* K = (const float*)d_in[1];
    const float* V = (const float*)d_in[2];
    const void*  M = d_in[3];

    float* out  = (float*)d_out;
    float* ctx  = out;
    float* attn = out + NQK;

    cudaFuncSetAttribute(fused_attn_kernel,
                         cudaFuncAttributeMaxDynamicSharedMemorySize, FUSED_SMEM);

    probe_mask_kernel<<<1, 256>>>(M);
    prep_mask_kernel<<<(unsigned)((size_t)BB * SS * SS / 32 / 256), 256>>>(M);
    prep_qk_kernel<<<(unsigned)((NQK / 4 + 255) / 256), 256>>>(Q, K);

    dim3 g(SS / 64, BB * HH);
    fused_attn_kernel<<<g, 256, FUSED_SMEM>>>(attn, V, ctx);
}